// round 12
// baseline (speedup 1.0000x reference)
#include <cuda_runtime.h>
#include <cuda_bf16.h>

// Problem constants: H=32, T=8192, D=128
#define RP_H 32
#define RP_T 8192
#define RP_D 128
#define RP_ROWS (RP_H * RP_T)          // 262144
#define RP_HPW 4                       // heads per warp
#define RP_HG (RP_H / RP_HPW)          // 8 head groups
#define RP_THREADS 256                 // 8 warps/block
#define RP_TPB 8                       // t-values per block (1 per warp)
#define RP_TBLOCKS (RP_T / RP_TPB)     // 1024
#define RP_BLOCKS (RP_HG * RP_TBLOCKS) // 8192

// 256-bit global ops (sm_100+): one instruction moves 8 floats per lane.
__device__ __forceinline__ void ldg256_cs(const float* p, float* r) {
    asm volatile("ld.global.cs.v8.b32 {%0,%1,%2,%3,%4,%5,%6,%7}, [%8];"
        : "=f"(r[0]), "=f"(r[1]), "=f"(r[2]), "=f"(r[3]),
          "=f"(r[4]), "=f"(r[5]), "=f"(r[6]), "=f"(r[7])
        : "l"(p));
}
__device__ __forceinline__ void ldg256(const float* p, float* r) {
    asm volatile("ld.global.v8.b32 {%0,%1,%2,%3,%4,%5,%6,%7}, [%8];"
        : "=f"(r[0]), "=f"(r[1]), "=f"(r[2]), "=f"(r[3]),
          "=f"(r[4]), "=f"(r[5]), "=f"(r[6]), "=f"(r[7])
        : "l"(p));
}
__device__ __forceinline__ void stg256_cs(float* p, const float* r) {
    asm volatile("st.global.cs.v8.b32 [%0], {%1,%2,%3,%4,%5,%6,%7,%8};"
        :: "l"(p),
           "f"(r[0]), "f"(r[1]), "f"(r[2]), "f"(r[3]),
           "f"(r[4]), "f"(r[5]), "f"(r[6]), "f"(r[7])
        : "memory");
}

// One warp = one t, 4 heads. Each lane covers 8 consecutive floats; a 128-float
// row spans 16 lanes, so each 256-bit instruction moves TWO head-rows:
//   group g = lane>>4 selects the row within a pair; li = lane&15 is the
//   position in the row (floats [li*8, li*8+8)).
// Rotation partner (i +/- 64) lives at lane^8 within the 16-lane group.
__global__ __launch_bounds__(RP_THREADS, 4) void rope_minmax_kernel(
    const float* __restrict__ x,
    const float* __restrict__ cosb,
    const float* __restrict__ sinb,
    float* __restrict__ out,
    float* __restrict__ obs_max,
    float* __restrict__ obs_min)
{
    const unsigned FULL = 0xffffffffu;
    int wid  = threadIdx.x >> 5;
    int lane = threadIdx.x & 31;
    int g    = lane >> 4;                        // row-within-pair (0/1)
    int li   = lane & 15;                        // position in row
    int hg   = blockIdx.x >> 10;                 // head group 0..7
    int tb   = blockIdx.x & (RP_TBLOCKS - 1);    // t-block within group
    int t    = tb * RP_TPB + wid;                // this warp's t
    int h0   = hg * RP_HPW;                      // first head

    // ---- DRAM-bound x loads first: 2 independent 256-bit loads (4 rows) ----
    float v0[8], v1[8];
    {
        size_t rowA = (size_t)(h0 + g) * RP_T + t;       // pair 0: heads h0, h0+1
        size_t rowB = (size_t)(h0 + 2 + g) * RP_T + t;   // pair 1: heads h0+2, h0+3
        ldg256_cs(x + rowA * RP_D + li * 8, v0);
        ldg256_cs(x + rowB * RP_D + li * 8, v1);
    }

    // ---- table loads (both lane groups read the same row -> L1 broadcast) ----
    float c[8], s[8];
    ldg256(cosb + (size_t)t * RP_D + li * 8, c);
    ldg256(sinb + (size_t)t * RP_D + li * 8, s);

    // rotated[i] = -x[i+64] for i<64, +x[i-64] for i>=64 ; partner at lane^8
    float sign = (lane & 8) ? 1.0f : -1.0f;
    #pragma unroll
    for (int k = 0; k < 8; k++) s[k] *= sign;

    float o0[8], o1[8];
    #pragma unroll
    for (int k = 0; k < 8; k++) {
        float p0 = __shfl_xor_sync(FULL, v0[k], 8);
        float p1 = __shfl_xor_sync(FULL, v1[k], 8);
        o0[k] = fmaf(p0, s[k], v0[k] * c[k]);
        o1[k] = fmaf(p1, s[k], v1[k] * c[k]);
    }

    // ---- 256-bit streaming stores ----
    {
        size_t rowA = (size_t)(h0 + g) * RP_T + t;
        size_t rowB = (size_t)(h0 + 2 + g) * RP_T + t;
        stg256_cs(out + rowA * RP_D + li * 8, o0);
        stg256_cs(out + rowB * RP_D + li * 8, o1);
    }

    // ---- per-lane then segmented (16-lane) butterfly min/max ----
    float mx0 = o0[0], mn0 = o0[0], mx1 = o1[0], mn1 = o1[0];
    #pragma unroll
    for (int k = 1; k < 8; k++) {
        mx0 = fmaxf(mx0, o0[k]); mn0 = fminf(mn0, o0[k]);
        mx1 = fmaxf(mx1, o1[k]); mn1 = fminf(mn1, o1[k]);
    }
    #pragma unroll
    for (int off = 8; off > 0; off >>= 1) {
        mx0 = fmaxf(mx0, __shfl_xor_sync(FULL, mx0, off));
        mn0 = fminf(mn0, __shfl_xor_sync(FULL, mn0, off));
        mx1 = fmaxf(mx1, __shfl_xor_sync(FULL, mx1, off));
        mn1 = fminf(mn1, __shfl_xor_sync(FULL, mn1, off));
    }

    // li==0 lanes (lane 0 and 16) hold their group's row stats
    if (li == 0) {
        size_t rowA = (size_t)(h0 + g) * RP_T + t;
        size_t rowB = (size_t)(h0 + 2 + g) * RP_T + t;
        obs_max[rowA] = mx0;  obs_min[rowA] = mn0;
        obs_max[rowB] = mx1;  obs_min[rowB] = mn1;
    }
}

extern "C" void kernel_launch(void* const* d_in, const int* in_sizes, int n_in,
                              void* d_out, int out_size) {
    // Input order: x, scale_x (unused), cos, scale_cos (unused), sin, scale_sin (unused)
    const float* x    = (const float*)d_in[0];
    const float* cosb = (const float*)d_in[2];
    const float* sinb = (const float*)d_in[4];

    float* out     = (float*)d_out;                    // H*T*D
    float* obs_max = out + (size_t)RP_ROWS * RP_D;     // H*T
    float* obs_min = obs_max + (size_t)RP_ROWS;        // H*T

    rope_minmax_kernel<<<RP_BLOCKS, RP_THREADS>>>(x, cosb, sinb, out, obs_max, obs_min);
}

// round 13
// speedup vs baseline: 1.0402x; 1.0402x over previous
#include <cuda_runtime.h>
#include <cuda_bf16.h>

// Problem constants: H=32, T=8192, D=128
#define RP_H 32
#define RP_T 8192
#define RP_D 128
#define RP_ROWS (RP_H * RP_T)          // 262144
#define RP_HPW 4                       // heads per warp (cos/sin register reuse)
#define RP_HG (RP_H / RP_HPW)          // 8 head groups
#define RP_THREADS 256                 // 8 warps/block
#define RP_TPB 8                       // t-values per block (1 per warp)
#define RP_TBLOCKS (RP_T / RP_TPB)     // 1024
#define RP_BLOCKS (RP_HG * RP_TBLOCKS) // 8192

// Order-preserving float->u32 map (for redux.sync min/max on floats)
__device__ __forceinline__ unsigned f2ord(float f) {
    unsigned u = __float_as_uint(f);
    return u ^ ((unsigned)((int)u >> 31) | 0x80000000u);
}
__device__ __forceinline__ float ord2f(unsigned u) {
    unsigned m = (unsigned)((int)(~u) >> 31) | 0x80000000u;
    return __uint_as_float(u ^ m);
}

// R6 structure (best verified: one warp = one t, 4 heads; tables loaded once;
// x via LDG.128.CS front-batched; out via STG.128.CS; 48 warps/SM) with the
// reduction tail swapped to redux.sync: per-warp MIO ops 56 -> 24.
__global__ __launch_bounds__(RP_THREADS, 6) void rope_minmax_kernel(
    const float* __restrict__ x,
    const float* __restrict__ cosb,
    const float* __restrict__ sinb,
    float* __restrict__ out,
    float* __restrict__ obs_max,
    float* __restrict__ obs_min)
{
    const unsigned FULL = 0xffffffffu;
    int wid  = threadIdx.x >> 5;
    int lane = threadIdx.x & 31;
    int hg   = blockIdx.x >> 10;                 // head group 0..7
    int tb   = blockIdx.x & (RP_TBLOCKS - 1);    // t-block within group
    int t    = tb * RP_TPB + wid;                // this warp's t
    int h0   = hg * RP_HPW;                      // first head

    // ---- DRAM-bound x loads first: 4 independent LDG.128.CS (4 heads, same t) ----
    float4 v[RP_HPW];
    #pragma unroll
    for (int j = 0; j < RP_HPW; j++) {
        size_t row = (size_t)(h0 + j) * RP_T + t;
        v[j] = __ldcs(reinterpret_cast<const float4*>(x + row * RP_D) + lane);
    }

    // ---- table loads once (default policy: reused across heads, L2-resident) ----
    float4 c = reinterpret_cast<const float4*>(cosb + (size_t)t * RP_D)[lane];
    float4 s = reinterpret_cast<const float4*>(sinb + (size_t)t * RP_D)[lane];

    float sign = (lane < 16) ? -1.0f : 1.0f;
    float4 sgs = make_float4(sign * s.x, sign * s.y, sign * s.z, sign * s.w);
    unsigned mxu[RP_HPW], mnu[RP_HPW];

    #pragma unroll
    for (int j = 0; j < RP_HPW; j++) {
        // partner half (elements i +/- 64) lives in lane ^ 16
        float4 p;
        p.x = __shfl_xor_sync(FULL, v[j].x, 16);
        p.y = __shfl_xor_sync(FULL, v[j].y, 16);
        p.z = __shfl_xor_sync(FULL, v[j].z, 16);
        p.w = __shfl_xor_sync(FULL, v[j].w, 16);

        float4 o;
        o.x = fmaf(p.x, sgs.x, v[j].x * c.x);
        o.y = fmaf(p.y, sgs.y, v[j].y * c.y);
        o.z = fmaf(p.z, sgs.z, v[j].z * c.z);
        o.w = fmaf(p.w, sgs.w, v[j].w * c.w);

        size_t row = (size_t)(h0 + j) * RP_T + t;
        __stcs(reinterpret_cast<float4*>(out + row * RP_D) + lane, o);

        float mx = fmaxf(fmaxf(o.x, o.y), fmaxf(o.z, o.w));
        float mn = fminf(fminf(o.x, o.y), fminf(o.z, o.w));
        mxu[j] = f2ord(mx);
        mnu[j] = f2ord(mn);
    }

    // ---- warp reductions: one redux.sync per row per stat (8 MIO ops total) ----
    #pragma unroll
    for (int j = 0; j < RP_HPW; j++) {
        mxu[j] = __reduce_max_sync(FULL, mxu[j]);
        mnu[j] = __reduce_min_sync(FULL, mnu[j]);
    }

    // Every lane holds all results: lanes 0..3 store their row's stats.
    if (lane < RP_HPW) {
        size_t row = (size_t)(h0 + lane) * RP_T + t;
        float omx = ord2f(mxu[0]), omn = ord2f(mnu[0]);
        #pragma unroll
        for (int j = 1; j < RP_HPW; j++) {
            if (lane == j) { omx = ord2f(mxu[j]); omn = ord2f(mnu[j]); }
        }
        obs_max[row] = omx;
        obs_min[row] = omn;
    }
}

extern "C" void kernel_launch(void* const* d_in, const int* in_sizes, int n_in,
                              void* d_out, int out_size) {
    // Input order: x, scale_x (unused), cos, scale_cos (unused), sin, scale_sin (unused)
    const float* x    = (const float*)d_in[0];
    const float* cosb = (const float*)d_in[2];
    const float* sinb = (const float*)d_in[4];

    float* out     = (float*)d_out;                    // H*T*D
    float* obs_max = out + (size_t)RP_ROWS * RP_D;     // H*T
    float* obs_min = obs_max + (size_t)RP_ROWS;        // H*T

    rope_minmax_kernel<<<RP_BLOCKS, RP_THREADS>>>(x, cosb, sinb, out, obs_max, obs_min);
}

// round 14
// speedup vs baseline: 1.0471x; 1.0066x over previous
#include <cuda_runtime.h>
#include <cuda_bf16.h>

// Problem constants: H=32, T=8192, D=128
#define RP_H 32
#define RP_T 8192
#define RP_D 128
#define RP_ROWS (RP_H * RP_T)          // 262144
#define RP_HPW 4                       // heads per warp (cos/sin register reuse)
#define RP_HG (RP_H / RP_HPW)          // 8 head groups
#define RP_THREADS 256                 // 8 warps/block
#define RP_TPB 8                       // t-values per block (1 per warp)
#define RP_TBLOCKS (RP_T / RP_TPB)     // 1024
#define RP_BLOCKS (RP_HG * RP_TBLOCKS) // 8192

// FINAL (best verified 43.49us, ~93% of achievable mixed-R/W HBM roofline):
// - one warp = one t, 4 heads; cos/sin loaded ONCE per warp, reused for the
//   4 x-rows (4x less L2 table traffic — LTS service was the binding resource)
// - x: 4 front-batched LDG.128.CS (read-once, evict-first, MLP=4/warp)
// - out: STG.128.CS (write-once streaming)
// - rotation partner (i +/- 64) via shfl_xor(16): x read exactly once
// - warps in a block take consecutive t -> dense 4KB chunks per head
// - __launch_bounds__(256,6): regs=40, 48 warps/SM resident
__global__ __launch_bounds__(RP_THREADS, 6) void rope_minmax_kernel(
    const float* __restrict__ x,
    const float* __restrict__ cosb,
    const float* __restrict__ sinb,
    float* __restrict__ out,
    float* __restrict__ obs_max,
    float* __restrict__ obs_min)
{
    const unsigned FULL = 0xffffffffu;
    int wid  = threadIdx.x >> 5;
    int lane = threadIdx.x & 31;
    int hg   = blockIdx.x >> 10;                 // head group 0..7
    int tb   = blockIdx.x & (RP_TBLOCKS - 1);    // t-block within group
    int t    = tb * RP_TPB + wid;                // this warp's t
    int h0   = hg * RP_HPW;                      // first head

    // ---- DRAM-bound x loads first: 4 independent LDG.128.CS (4 heads, same t) ----
    float4 v[RP_HPW];
    #pragma unroll
    for (int j = 0; j < RP_HPW; j++) {
        size_t row = (size_t)(h0 + j) * RP_T + t;
        v[j] = __ldcs(reinterpret_cast<const float4*>(x + row * RP_D) + lane);
    }

    // ---- table loads once (default policy: reused across heads, L2-resident) ----
    float4 c = reinterpret_cast<const float4*>(cosb + (size_t)t * RP_D)[lane];
    float4 s = reinterpret_cast<const float4*>(sinb + (size_t)t * RP_D)[lane];

    float sign = (lane < 16) ? -1.0f : 1.0f;
    float4 sgs = make_float4(sign * s.x, sign * s.y, sign * s.z, sign * s.w);
    float mx[RP_HPW], mn[RP_HPW];

    #pragma unroll
    for (int j = 0; j < RP_HPW; j++) {
        // partner half (elements i +/- 64) lives in lane ^ 16
        float4 p;
        p.x = __shfl_xor_sync(FULL, v[j].x, 16);
        p.y = __shfl_xor_sync(FULL, v[j].y, 16);
        p.z = __shfl_xor_sync(FULL, v[j].z, 16);
        p.w = __shfl_xor_sync(FULL, v[j].w, 16);

        float4 o;
        o.x = fmaf(p.x, sgs.x, v[j].x * c.x);
        o.y = fmaf(p.y, sgs.y, v[j].y * c.y);
        o.z = fmaf(p.z, sgs.z, v[j].z * c.z);
        o.w = fmaf(p.w, sgs.w, v[j].w * c.w);

        size_t row = (size_t)(h0 + j) * RP_T + t;
        __stcs(reinterpret_cast<float4*>(out + row * RP_D) + lane, o);

        mx[j] = fmaxf(fmaxf(o.x, o.y), fmaxf(o.z, o.w));
        mn[j] = fminf(fminf(o.x, o.y), fminf(o.z, o.w));
    }

    // ---- 4 interleaved butterfly reductions (ILP hides SHFL latency) ----
    #pragma unroll
    for (int off = 16; off > 0; off >>= 1) {
        #pragma unroll
        for (int j = 0; j < RP_HPW; j++) {
            mx[j] = fmaxf(mx[j], __shfl_xor_sync(FULL, mx[j], off));
            mn[j] = fminf(mn[j], __shfl_xor_sync(FULL, mn[j], off));
        }
    }

    // After butterfly every lane holds the result: lanes 0..3 store their row's stats.
    if (lane < RP_HPW) {
        size_t row = (size_t)(h0 + lane) * RP_T + t;
        obs_max[row] = mx[lane];
        obs_min[row] = mn[lane];
    }
}

extern "C" void kernel_launch(void* const* d_in, const int* in_sizes, int n_in,
                              void* d_out, int out_size) {
    // Input order: x, scale_x (unused), cos, scale_cos (unused), sin, scale_sin (unused)
    const float* x    = (const float*)d_in[0];
    const float* cosb = (const float*)d_in[2];
    const float* sinb = (const float*)d_in[4];

    float* out     = (float*)d_out;                    // H*T*D
    float* obs_max = out + (size_t)RP_ROWS * RP_D;     // H*T
    float* obs_min = obs_max + (size_t)RP_ROWS;        // H*T

    rope_minmax_kernel<<<RP_BLOCKS, RP_THREADS>>>(x, cosb, sinb, out, obs_max, obs_min);
}